// round 11
// baseline (speedup 1.0000x reference)
#include <cuda_runtime.h>
#include <cuda_fp16.h>
#include <cstdint>
#include <math.h>

#define Bb 2
#define Tt 2048
#define Cc 2048
#define Hh 16
#define Dd 128
#define NTOK (Bb*Tt)   // 4096

// Scratch (device globals: no runtime allocation allowed)
__device__ __half g_xh [(size_t)NTOK*Cc];
__device__ __half g_wqh[(size_t)Cc*Cc];
__device__ __half g_wkh[(size_t)Cc*Cc];
__device__ __half g_wvh[(size_t)Cc*Cc];
__device__ __half g_wph[(size_t)Cc*Cc];
__device__ __half g_qh [(size_t)NTOK*Cc];
__device__ __half g_kh [(size_t)NTOK*Cc];
__device__ __half g_vh [(size_t)NTOK*Cc];
__device__ __half g_ctxh[(size_t)NTOK*Cc];

// ===========================================================================
// helpers
// ===========================================================================
__device__ __forceinline__ uint32_t smem_u32(const void* p) {
    uint32_t a;
    asm("{ .reg .u64 t; cvta.to.shared.u64 t, %1; cvt.u32.u64 %0, t; }" : "=r"(a) : "l"(p));
    return a;
}
__device__ __forceinline__ void cp_async16(uint32_t dst, const void* src) {
    asm volatile("cp.async.cg.shared.global [%0], [%1], 16;" :: "r"(dst), "l"(src) : "memory");
}
__device__ __forceinline__ void cp_commit() {
    asm volatile("cp.async.commit_group;" ::: "memory");
}
__device__ __forceinline__ void cp_wait2() {
    asm volatile("cp.async.wait_group 2;" ::: "memory");
}
__device__ __forceinline__ void cp_wait1() {
    asm volatile("cp.async.wait_group 1;" ::: "memory");
}
__device__ __forceinline__ void cp_wait0() {
    asm volatile("cp.async.wait_group 0;" ::: "memory");
}
__device__ __forceinline__ void ldsm_x4(uint32_t* r, uint32_t addr) {
    asm volatile("ldmatrix.sync.aligned.m8n8.x4.shared.b16 {%0,%1,%2,%3}, [%4];"
                 : "=r"(r[0]), "=r"(r[1]), "=r"(r[2]), "=r"(r[3]) : "r"(addr));
}
__device__ __forceinline__ void ldsm_x4_t(uint32_t* r, uint32_t addr) {
    asm volatile("ldmatrix.sync.aligned.m8n8.x4.trans.shared.b16 {%0,%1,%2,%3}, [%4];"
                 : "=r"(r[0]), "=r"(r[1]), "=r"(r[2]), "=r"(r[3]) : "r"(addr));
}
// m16n8k16 fp16 MMA, fp32 accumulate
__device__ __forceinline__ void mma_f16(float* c, const uint32_t* a, const uint32_t* b) {
    asm volatile(
        "mma.sync.aligned.m16n8k16.row.col.f32.f16.f16.f32 "
        "{%0,%1,%2,%3}, {%4,%5,%6,%7}, {%8,%9}, {%0,%1,%2,%3};"
        : "+f"(c[0]), "+f"(c[1]), "+f"(c[2]), "+f"(c[3])
        : "r"(a[0]), "r"(a[1]), "r"(a[2]), "r"(a[3]), "r"(b[0]), "r"(b[1]));
}

// ===========================================================================
// fp32 -> fp16 conversion (z selects buffer); Wq gets 1/sqrt(D) folded in
// ===========================================================================
__global__ void __launch_bounds__(256) tohalf_all(
    const float4* __restrict__ x,  __half* __restrict__ xr,
    const float4* __restrict__ w0, __half* __restrict__ r0,
    const float4* __restrict__ w1, __half* __restrict__ r1,
    const float4* __restrict__ w2, __half* __restrict__ r2,
    const float4* __restrict__ w3, __half* __restrict__ r3)
{
    const int z = blockIdx.z;
    const float4* src; __half* dst; int n4;
    float sc = 1.0f;
    if      (z == 0) { src = x;  dst = xr; n4 = NTOK*Cc/4; }
    else if (z == 1) { src = w0; dst = r0; n4 = Cc*Cc/4; sc = 0.08838834764831845f; }
    else if (z == 2) { src = w1; dst = r1; n4 = Cc*Cc/4; }
    else if (z == 3) { src = w2; dst = r2; n4 = Cc*Cc/4; }
    else             { src = w3; dst = r3; n4 = Cc*Cc/4; }
    int i = blockIdx.x * blockDim.x + threadIdx.x;
    if (i < n4) {
        float4 v = src[i];
        *(__half2*)(dst + (size_t)i*4)     = __floats2half2_rn(v.x*sc, v.y*sc);
        *(__half2*)(dst + (size_t)i*4 + 2) = __floats2half2_rn(v.z*sc, v.w*sc);
    }
}

// ===========================================================================
// fp16 mma.sync GEMM (unchanged from R10): CTA 128x128, 256 thr, BK=64,
// 3 stages, 96KB smem -> 2 CTAs/SM.
// ===========================================================================
#define G_BK     64
#define G_TBY    (128*128)
#define G_STAGES 3
#define G_SMEM   (G_STAGES*2*G_TBY)            // 98304
#define G_NSTEP  (Cc / G_BK)                   // 32

template<bool HALF_OUT>
__device__ __forceinline__ void gemm_body(const __half* __restrict__ A,
                                          const __half* __restrict__ W,
                                          const float* __restrict__ bias,
                                          float* __restrict__ Cf,
                                          __half* __restrict__ Ch)
{
    extern __shared__ char smc[];
    const uint32_t asb = smem_u32(smc);
    const uint32_t bsb = asb + G_STAGES * G_TBY;

    const int tid  = threadIdx.x;
    const int lane = tid & 31;
    const int warp = tid >> 5;
    const int n0 = blockIdx.x * 128;
    const int m0 = blockIdx.y * 128;
    const int wm = (warp & 1) * 64;
    const int wn = (warp >> 1) * 32;
    const int fr = lane >> 2;
    const int fc = lane & 3;

    const int a_msel = (lane >> 3) & 1;
    const int a_ksel = lane >> 4;
    const int b_nsel = (lane >> 4) & 1;
    const int b_ksel = (lane >> 3) & 1;
    uint32_t a_off[4], a_sw[4], b_off[2], b_sw[2];
    #pragma unroll
    for (int mi = 0; mi < 4; mi++) {
        const int r = wm + mi*16 + a_msel*8 + (lane & 7);
        a_off[mi] = (uint32_t)r * 128;
        a_sw[mi]  = (uint32_t)(r & 7);
    }
    #pragma unroll
    for (int pi = 0; pi < 2; pi++) {
        const int n = wn + pi*16 + b_nsel*8 + (lane & 7);
        b_off[pi] = (uint32_t)n * 128;
        b_sw[pi]  = (uint32_t)(n & 7);
    }

    const int lr  = tid >> 1;
    const int lj0 = (tid & 1) * 4;
    const __half* Ag = A + (size_t)(m0 + lr) * Cc;
    const __half* Wg = W + (size_t)(n0 + lr) * Cc;
    const uint32_t swr = (uint32_t)(lr & 7);

    float acc[4][4][4];
    #pragma unroll
    for (int i = 0; i < 4; i++)
        #pragma unroll
        for (int j = 0; j < 4; j++)
            #pragma unroll
            for (int q = 0; q < 4; q++) acc[i][j][q] = 0.f;

    #define G_LOAD(s, st) do {                                                  \
        const uint32_t sa = asb + (st) * G_TBY;                                  \
        const uint32_t sb = bsb + (st) * G_TBY;                                  \
        const int kof = (s) * G_BK;                                              \
        _Pragma("unroll")                                                        \
        for (int j = 0; j < 4; j++) {                                            \
            const int ch = lj0 + j;                                              \
            const uint32_t dof = lr*128 + (((uint32_t)ch ^ swr) << 4);           \
            cp_async16(sa + dof, Ag + kof + ch*8);                               \
            cp_async16(sb + dof, Wg + kof + ch*8);                               \
        }                                                                        \
    } while (0)

    G_LOAD(0, 0); cp_commit();
    G_LOAD(1, 1); cp_commit();

    for (int s = 0; s < G_NSTEP; s++) {
        cp_wait1();
        __syncthreads();
        if (s + 2 < G_NSTEP) { G_LOAD(s + 2, (s + 2) % G_STAGES); }
        cp_commit();

        const uint32_t A_sa = asb + (s % G_STAGES) * G_TBY;
        const uint32_t B_sa = bsb + (s % G_STAGES) * G_TBY;

        #pragma unroll
        for (int ks = 0; ks < 4; ks++) {
            const uint32_t ka  = (uint32_t)(2*ks + a_ksel);
            const uint32_t kb_ = (uint32_t)(2*ks + b_ksel);
            uint32_t af[4][4], bf[2][4];
            #pragma unroll
            for (int mi = 0; mi < 4; mi++)
                ldsm_x4(af[mi], A_sa + a_off[mi] + ((ka ^ a_sw[mi]) << 4));
            #pragma unroll
            for (int pi = 0; pi < 2; pi++)
                ldsm_x4(bf[pi], B_sa + b_off[pi] + ((kb_ ^ b_sw[pi]) << 4));
            #pragma unroll
            for (int mi = 0; mi < 4; mi++)
                #pragma unroll
                for (int ni = 0; ni < 4; ni++)
                    mma_f16(acc[mi][ni], af[mi], &bf[ni >> 1][(ni & 1) * 2]);
        }
    }
    #undef G_LOAD
    __syncthreads();

    #pragma unroll
    for (int mi = 0; mi < 4; mi++) {
        const int r0 = m0 + wm + mi*16 + fr;
        #pragma unroll
        for (int ni = 0; ni < 4; ni++) {
            const int col = n0 + wn + ni*8 + fc*2;
            if (HALF_OUT) {
                *(__half2*)(Ch + (size_t)r0       * Cc + col) =
                    __floats2half2_rn(acc[mi][ni][0], acc[mi][ni][1]);
                *(__half2*)(Ch + (size_t)(r0 + 8) * Cc + col) =
                    __floats2half2_rn(acc[mi][ni][2], acc[mi][ni][3]);
            } else {
                const float b0 = __ldg(bias + col), b1 = __ldg(bias + col + 1);
                *(float2*)(Cf + (size_t)r0       * Cc + col) =
                    make_float2(acc[mi][ni][0] + b0, acc[mi][ni][1] + b1);
                *(float2*)(Cf + (size_t)(r0 + 8) * Cc + col) =
                    make_float2(acc[mi][ni][2] + b0, acc[mi][ni][3] + b1);
            }
        }
    }
}

__global__ void __launch_bounds__(256, 2)
gemm_out(const __half* __restrict__ A, const __half* __restrict__ W,
         const float* __restrict__ bias, float* __restrict__ C) {
    gemm_body<false>(A, W, bias, C, nullptr);
}

__global__ void __launch_bounds__(256, 2)
gemm_qkv(const __half* __restrict__ A,
         const __half* __restrict__ W0, const __half* __restrict__ W1,
         const __half* __restrict__ W2,
         __half* __restrict__ C0, __half* __restrict__ C1, __half* __restrict__ C2) {
    const __half* W = (blockIdx.z == 0) ? W0 : (blockIdx.z == 1) ? W1 : W2;
    __half*       C = (blockIdx.z == 0) ? C0 : (blockIdx.z == 1) ? C1 : C2;
    gemm_body<true>(A, W, nullptr, nullptr, C);
}

// ===========================================================================
// Flash-attention, fp16 mma.sync. K double-buffered, V single-buffered.
// smem 72KB -> 3 CTAs/SM. Scale pre-folded into Wq (q already scaled).
// ===========================================================================
#define AT_Q  0
#define AT_K0 16384      // K stages at 16384, 32768
#define AT_V  49152
#define AT_P  65536
#define AT_SMEM 73728

__global__ void __launch_bounds__(128, 3) attn_f16(const int* __restrict__ pm)
{
    extern __shared__ char smc[];
    const uint32_t sb  = smem_u32(smc);
    const uint32_t qsb = sb + AT_Q;
    const uint32_t vsb = sb + AT_V;
    const uint32_t psb = sb + AT_P;

    const int qb = (gridDim.x - 1) - blockIdx.x;   // descending order
    const int h  = blockIdx.y;
    const int b  = blockIdx.z;
    const int tid  = threadIdx.x;
    const int lane = tid & 31;
    const int warp = tid >> 5;
    const int fr = lane >> 2;
    const int fc = lane & 3;

    const int a_msel = (lane >> 3) & 1;
    const int a_ksel = lane >> 4;
    const int b_nsel = (lane >> 4) & 1;
    const int b_ksel = (lane >> 3) & 1;
    const int v_ssel = (lane >> 3) & 1;
    const int v_dsel = (lane >> 4) & 1;
    const int a_row  = warp*16 + a_msel*8 + (lane & 7);

    const size_t hoff = (size_t)h * Dd;
    const __half* Qg = g_qh + (size_t)b * Tt * Cc + hoff;
    const __half* Kg = g_kh + (size_t)b * Tt * Cc + hoff;
    const __half* Vg = g_vh + (size_t)b * Tt * Cc + hoff;
    const int q0 = qb * 64;

    const int lrow = tid >> 1;
    const int lch0 = (tid & 1) * 8;
    const uint32_t lsw = (uint32_t)(lrow & 7);

    #define AT_LOADK(kt, st) do {                                                  \
        const uint32_t kb_ = sb + AT_K0 + (st)*16384;                              \
        _Pragma("unroll")                                                          \
        for (int j = 0; j < 8; j++) {                                              \
            const int ch = lch0 + j;                                               \
            cp_async16(kb_ + lrow*256 + (((uint32_t)ch ^ lsw) << 4),               \
                       Kg + (size_t)((kt)*64 + lrow)*Cc + ch*8);                   \
        }                                                                          \
        cp_commit();                                                               \
    } while (0)

    #define AT_LOADV(kt) do {                                                      \
        _Pragma("unroll")                                                          \
        for (int j = 0; j < 8; j++) {                                              \
            const int ch = lch0 + j;                                               \
            cp_async16(vsb + lrow*256 + (((uint32_t)ch ^ lsw) << 4),               \
                       Vg + (size_t)((kt)*64 + lrow)*Cc + ch*8);                   \
        }                                                                          \
        cp_commit();                                                               \
    } while (0)

    // ---- prologue: Q + K(0) ----
    #pragma unroll
    for (int j = 0; j < 8; j++) {
        const int ch = lch0 + j;
        cp_async16(qsb + lrow*256 + (((uint32_t)ch ^ lsw) << 4),
                   Qg + (size_t)(q0 + lrow)*Cc + ch*8);
    }
    cp_commit();
    AT_LOADK(0, 0);
    cp_wait1();          // Q resident (K(0) may still fly)
    __syncthreads();

    uint32_t qf[8][4];
    #pragma unroll
    for (int kb = 0; kb < 8; kb++)
        ldsm_x4(qf[kb], qsb + a_row*256 + (((uint32_t)(2*kb + a_ksel) ^ (uint32_t)(a_row & 7)) << 4));

    const int rowA = q0 + warp*16 + fr;
    const int rowB = rowA + 8;
    const int pmA = pm[b*Tt + rowA];
    const int pmB = pm[b*Tt + rowB];
    const int prA = warp*16 + fr;

    float o[16][4];
    #pragma unroll
    for (int i = 0; i < 16; i++)
        #pragma unroll
        for (int j = 0; j < 4; j++) o[i][j] = 0.f;
    float mA = -INFINITY, mB = -INFINITY, lA = 0.f, lB = 0.f;

    for (int kt = 0; kt <= qb; kt++) {
        const int cur = kt & 1;
        const bool more = (kt + 1 <= qb);

        AT_LOADV(kt);                        // V buffer free (barrier at loop end)
        if (more) AT_LOADK(kt + 1, cur ^ 1); // prefetch next K
        if (more) cp_wait2(); else cp_wait1();   // K(kt) + older resident
        __syncthreads();

        const uint32_t ksb = sb + AT_K0 + cur*16384;

        // ---- S = Q K^T (scale pre-folded into q) ----
        float sa[8][4];
        #pragma unroll
        for (int ni = 0; ni < 8; ni++)
            #pragma unroll
            for (int j = 0; j < 4; j++) sa[ni][j] = 0.f;

        #pragma unroll
        for (int kb = 0; kb < 8; kb++) {
            uint32_t bq[4][4];
            #pragma unroll
            for (int pi = 0; pi < 4; pi++) {
                const int n = pi*16 + b_nsel*8 + (lane & 7);
                ldsm_x4(bq[pi], ksb + n*256 + (((uint32_t)(2*kb + b_ksel) ^ (uint32_t)(n & 7)) << 4));
            }
            #pragma unroll
            for (int ni = 0; ni < 8; ni++)
                mma_f16(sa[ni], qf[kb], &bq[ni >> 1][(ni & 1) * 2]);
        }

        // ---- mask + online softmax ----
        float mxA = -INFINITY, mxB = -INFINITY;
        #pragma unroll
        for (int ni = 0; ni < 8; ni++) {
            const int c0 = kt*64 + ni*8 + 2*fc;
            float s0 = sa[ni][0], s1 = sa[ni][1];
            float s2 = sa[ni][2], s3 = sa[ni][3];
            if (pmA == 0) { s0 = -1e9f; s1 = -1e9f; }
            if (pmB == 0) { s2 = -1e9f; s3 = -1e9f; }
            if (kt == qb) {
                if (c0     > rowA) s0 = -INFINITY;
                if (c0 + 1 > rowA) s1 = -INFINITY;
                if (c0     > rowB) s2 = -INFINITY;
                if (c0 + 1 > rowB) s3 = -INFINITY;
            }
            sa[ni][0] = s0; sa[ni][1] = s1; sa[ni][2] = s2; sa[ni][3] = s3;
            mxA = fmaxf(mxA, fmaxf(s0, s1));
            mxB = fmaxf(mxB, fmaxf(s2, s3));
        }
        mxA = fmaxf(mxA, __shfl_xor_sync(0xffffffffu, mxA, 1));
        mxA = fmaxf(mxA, __shfl_xor_sync(0xffffffffu, mxA, 2));
        mxB = fmaxf(mxB, __shfl_xor_sync(0xffffffffu, mxB, 1));
        mxB = fmaxf(mxB, __shfl_xor_sync(0xffffffffu, mxB, 2));

        const float mnA = fmaxf(mA, mxA), mnB = fmaxf(mB, mxB);
        const float sfA = __expf(mA - mnA), sfB = __expf(mB - mnB);
        mA = mnA; mB = mnB;

        float suA = 0.f, suB = 0.f;
        #pragma unroll
        for (int ni = 0; ni < 8; ni++) {
            __half2 h01 = __floats2half2_rn(__expf(sa[ni][0] - mA), __expf(sa[ni][1] - mA));
            __half2 h23 = __floats2half2_rn(__expf(sa[ni][2] - mB), __expf(sa[ni][3] - mB));
            const float2 f01 = __half22float2(h01);
            const float2 f23 = __half22float2(h23);
            suA += f01.x + f01.y; suB += f23.x + f23.y;
            const uint32_t aoA = psb + prA*128     + (((uint32_t)ni ^ (uint32_t)(prA & 7))     << 4) + fc*4;
            const uint32_t aoB = psb + (prA+8)*128 + (((uint32_t)ni ^ (uint32_t)((prA+8) & 7)) << 4) + fc*4;
            *(__half2*)(smc + (aoA - sb)) = h01;
            *(__half2*)(smc + (aoB - sb)) = h23;
        }
        suA += __shfl_xor_sync(0xffffffffu, suA, 1);
        suA += __shfl_xor_sync(0xffffffffu, suA, 2);
        suB += __shfl_xor_sync(0xffffffffu, suB, 1);
        suB += __shfl_xor_sync(0xffffffffu, suB, 2);
        lA = lA*sfA + suA;
        lB = lB*sfB + suB;
        #pragma unroll
        for (int ni = 0; ni < 16; ni++) {
            o[ni][0] *= sfA; o[ni][1] *= sfA;
            o[ni][2] *= sfB; o[ni][3] *= sfB;
        }
        __syncwarp();   // P rows per-warp private

        // ---- V(kt) must be resident for all threads before PV ----
        if (more) cp_wait1(); else cp_wait0();
        __syncthreads();

        // ---- O += P V ----
        #pragma unroll
        for (int kb = 0; kb < 4; kb++) {
            uint32_t pa[4];
            ldsm_x4(pa, psb + a_row*128 + (((uint32_t)(2*kb + a_ksel) ^ (uint32_t)(a_row & 7)) << 4));
            #pragma unroll
            for (int di = 0; di < 8; di++) {
                uint32_t bv[4];
                const int sv = kb*16 + v_ssel*8 + (lane & 7);
                const uint32_t ch = (uint32_t)(2*di + v_dsel);
                ldsm_x4_t(bv, vsb + sv*256 + ((ch ^ (uint32_t)(sv & 7)) << 4));
                mma_f16(o[di*2    ], pa, &bv[0]);
                mma_f16(o[di*2 + 1], pa, &bv[2]);
            }
        }
        __syncthreads();   // V + K(cur) free before next iteration's loads
    }
    #undef AT_LOADK
    #undef AT_LOADV

    const float iA = 1.f / lA, iB = 1.f / lB;
    __half* cpA = g_ctxh + (size_t)(b*Tt + rowA)*Cc + hoff;
    __half* cpB = g_ctxh + (size_t)(b*Tt + rowB)*Cc + hoff;
    #pragma unroll
    for (int ni = 0; ni < 16; ni++) {
        const int d0 = ni*8 + 2*fc;
        *(__half2*)(cpA + d0) = __floats2half2_rn(o[ni][0]*iA, o[ni][1]*iA);
        *(__half2*)(cpB + d0) = __floats2half2_rn(o[ni][2]*iB, o[ni][3]*iB);
    }
}

// ===========================================================================
extern "C" void kernel_launch(void* const* d_in, const int* in_sizes, int n_in,
                              void* d_out, int out_size)
{
    (void)in_sizes; (void)n_in; (void)out_size;
    const float* x  = (const float*)d_in[0];
    const int*   pm = (const int*)  d_in[1];
    const float* Wq = (const float*)d_in[2];
    const float* Wk = (const float*)d_in[3];
    const float* Wv = (const float*)d_in[4];
    const float* Wp = (const float*)d_in[5];
    const float* bp = (const float*)d_in[6];
    float* out = (float*)d_out;

    __half *xh, *wqh, *wkh, *wvh, *wph, *qh, *kh, *vh, *ctxh;
    cudaGetSymbolAddress((void**)&xh,   g_xh);
    cudaGetSymbolAddress((void**)&wqh,  g_wqh);
    cudaGetSymbolAddress((void**)&wkh,  g_wkh);
    cudaGetSymbolAddress((void**)&wvh,  g_wvh);
    cudaGetSymbolAddress((void**)&wph,  g_wph);
    cudaGetSymbolAddress((void**)&qh,   g_qh);
    cudaGetSymbolAddress((void**)&kh,   g_kh);
    cudaGetSymbolAddress((void**)&vh,   g_vh);
    cudaGetSymbolAddress((void**)&ctxh, g_ctxh);

    const int nb = (NTOK*Cc/4 + 255) / 256;
    tohalf_all<<<dim3(nb, 1, 5), 256>>>(
        (const float4*)x,  xh,
        (const float4*)Wq, wqh,
        (const float4*)Wk, wkh,
        (const float4*)Wv, wvh,
        (const float4*)Wp, wph);

    cudaFuncSetAttribute(gemm_qkv, cudaFuncAttributeMaxDynamicSharedMemorySize, G_SMEM);
    cudaFuncSetAttribute(gemm_out, cudaFuncAttributeMaxDynamicSharedMemorySize, G_SMEM);
    cudaFuncSetAttribute(attn_f16, cudaFuncAttributeMaxDynamicSharedMemorySize, AT_SMEM);

    gemm_qkv<<<dim3(Cc/128, NTOK/128, 3), 256, G_SMEM>>>(xh, wqh, wkh, wvh, qh, kh, vh);
    attn_f16<<<dim3(Tt/64, Hh, Bb), 128, AT_SMEM>>>(pm);
    gemm_out<<<dim3(Cc/128, NTOK/128), 256, G_SMEM>>>(ctxh, wph, bp, out);
}

// round 12
// speedup vs baseline: 1.0293x; 1.0293x over previous
#include <cuda_runtime.h>
#include <cuda_fp16.h>
#include <cstdint>
#include <math.h>

#define Bb 2
#define Tt 2048
#define Cc 2048
#define Hh 16
#define Dd 128
#define NTOK (Bb*Tt)   // 4096

// Scratch (device globals: no runtime allocation allowed)
__device__ __half g_xh [(size_t)NTOK*Cc];
__device__ __half g_wqh[(size_t)Cc*Cc];
__device__ __half g_wkh[(size_t)Cc*Cc];
__device__ __half g_wvh[(size_t)Cc*Cc];
__device__ __half g_wph[(size_t)Cc*Cc];
__device__ __half g_qh [(size_t)NTOK*Cc];
__device__ __half g_kh [(size_t)NTOK*Cc];
__device__ __half g_vh [(size_t)NTOK*Cc];
__device__ __half g_ctxh[(size_t)NTOK*Cc];

// ===========================================================================
// helpers
// ===========================================================================
__device__ __forceinline__ uint32_t smem_u32(const void* p) {
    uint32_t a;
    asm("{ .reg .u64 t; cvta.to.shared.u64 t, %1; cvt.u32.u64 %0, t; }" : "=r"(a) : "l"(p));
    return a;
}
__device__ __forceinline__ void cp_async16(uint32_t dst, const void* src) {
    asm volatile("cp.async.cg.shared.global [%0], [%1], 16;" :: "r"(dst), "l"(src) : "memory");
}
__device__ __forceinline__ void cp_commit() {
    asm volatile("cp.async.commit_group;" ::: "memory");
}
__device__ __forceinline__ void cp_wait1() {
    asm volatile("cp.async.wait_group 1;" ::: "memory");
}
__device__ __forceinline__ void cp_wait0() {
    asm volatile("cp.async.wait_group 0;" ::: "memory");
}
__device__ __forceinline__ void ldsm_x4(uint32_t* r, uint32_t addr) {
    asm volatile("ldmatrix.sync.aligned.m8n8.x4.shared.b16 {%0,%1,%2,%3}, [%4];"
                 : "=r"(r[0]), "=r"(r[1]), "=r"(r[2]), "=r"(r[3]) : "r"(addr));
}
__device__ __forceinline__ void ldsm_x4_t(uint32_t* r, uint32_t addr) {
    asm volatile("ldmatrix.sync.aligned.m8n8.x4.trans.shared.b16 {%0,%1,%2,%3}, [%4];"
                 : "=r"(r[0]), "=r"(r[1]), "=r"(r[2]), "=r"(r[3]) : "r"(addr));
}
// m16n8k16 fp16 MMA, fp32 accumulate
__device__ __forceinline__ void mma_f16(float* c, const uint32_t* a, const uint32_t* b) {
    asm volatile(
        "mma.sync.aligned.m16n8k16.row.col.f32.f16.f16.f32 "
        "{%0,%1,%2,%3}, {%4,%5,%6,%7}, {%8,%9}, {%0,%1,%2,%3};"
        : "+f"(c[0]), "+f"(c[1]), "+f"(c[2]), "+f"(c[3])
        : "r"(a[0]), "r"(a[1]), "r"(a[2]), "r"(a[3]), "r"(b[0]), "r"(b[1]));
}
// raw MUFU ex2 (exp base 2); log2e folded into Wq so no multiply needed
__device__ __forceinline__ float exp2a(float x) {
    float y;
    asm("ex2.approx.f32 %0, %1;" : "=f"(y) : "f"(x));
    return y;
}

// ===========================================================================
// fp32 -> fp16 conversion; Wq gets (1/sqrt(D)) * log2(e) folded in
// ===========================================================================
__global__ void __launch_bounds__(256) tohalf_all(
    const float4* __restrict__ x,  __half* __restrict__ xr,
    const float4* __restrict__ w0, __half* __restrict__ r0,
    const float4* __restrict__ w1, __half* __restrict__ r1,
    const float4* __restrict__ w2, __half* __restrict__ r2,
    const float4* __restrict__ w3, __half* __restrict__ r3)
{
    const int z = blockIdx.z;
    const float4* src; __half* dst; int n4;
    float sc = 1.0f;
    if      (z == 0) { src = x;  dst = xr; n4 = NTOK*Cc/4; }
    else if (z == 1) { src = w0; dst = r0; n4 = Cc*Cc/4;
                       sc = 0.08838834764831845f * 1.4426950408889634f; }
    else if (z == 2) { src = w1; dst = r1; n4 = Cc*Cc/4; }
    else if (z == 3) { src = w2; dst = r2; n4 = Cc*Cc/4; }
    else             { src = w3; dst = r3; n4 = Cc*Cc/4; }
    int i = blockIdx.x * blockDim.x + threadIdx.x;
    if (i < n4) {
        float4 v = src[i];
        *(__half2*)(dst + (size_t)i*4)     = __floats2half2_rn(v.x*sc, v.y*sc);
        *(__half2*)(dst + (size_t)i*4 + 2) = __floats2half2_rn(v.z*sc, v.w*sc);
    }
}

// ===========================================================================
// fp16 mma.sync GEMM (unchanged): CTA 128x128, 256 thr, BK=64, 3 stages,
// 96KB smem -> 2 CTAs/SM.
// ===========================================================================
#define G_BK     64
#define G_TBY    (128*128)
#define G_STAGES 3
#define G_SMEM   (G_STAGES*2*G_TBY)            // 98304
#define G_NSTEP  (Cc / G_BK)                   // 32

template<bool HALF_OUT>
__device__ __forceinline__ void gemm_body(const __half* __restrict__ A,
                                          const __half* __restrict__ W,
                                          const float* __restrict__ bias,
                                          float* __restrict__ Cf,
                                          __half* __restrict__ Ch)
{
    extern __shared__ char smc[];
    const uint32_t asb = smem_u32(smc);
    const uint32_t bsb = asb + G_STAGES * G_TBY;

    const int tid  = threadIdx.x;
    const int lane = tid & 31;
    const int warp = tid >> 5;
    const int n0 = blockIdx.x * 128;
    const int m0 = blockIdx.y * 128;
    const int wm = (warp & 1) * 64;
    const int wn = (warp >> 1) * 32;
    const int fr = lane >> 2;
    const int fc = lane & 3;

    const int a_msel = (lane >> 3) & 1;
    const int a_ksel = lane >> 4;
    const int b_nsel = (lane >> 4) & 1;
    const int b_ksel = (lane >> 3) & 1;
    uint32_t a_off[4], a_sw[4], b_off[2], b_sw[2];
    #pragma unroll
    for (int mi = 0; mi < 4; mi++) {
        const int r = wm + mi*16 + a_msel*8 + (lane & 7);
        a_off[mi] = (uint32_t)r * 128;
        a_sw[mi]  = (uint32_t)(r & 7);
    }
    #pragma unroll
    for (int pi = 0; pi < 2; pi++) {
        const int n = wn + pi*16 + b_nsel*8 + (lane & 7);
        b_off[pi] = (uint32_t)n * 128;
        b_sw[pi]  = (uint32_t)(n & 7);
    }

    const int lr  = tid >> 1;
    const int lj0 = (tid & 1) * 4;
    const __half* Ag = A + (size_t)(m0 + lr) * Cc;
    const __half* Wg = W + (size_t)(n0 + lr) * Cc;
    const uint32_t swr = (uint32_t)(lr & 7);

    float acc[4][4][4];
    #pragma unroll
    for (int i = 0; i < 4; i++)
        #pragma unroll
        for (int j = 0; j < 4; j++)
            #pragma unroll
            for (int q = 0; q < 4; q++) acc[i][j][q] = 0.f;

    #define G_LOAD(s, st) do {                                                  \
        const uint32_t sa = asb + (st) * G_TBY;                                  \
        const uint32_t sb = bsb + (st) * G_TBY;                                  \
        const int kof = (s) * G_BK;                                              \
        _Pragma("unroll")                                                        \
        for (int j = 0; j < 4; j++) {                                            \
            const int ch = lj0 + j;                                              \
            const uint32_t dof = lr*128 + (((uint32_t)ch ^ swr) << 4);           \
            cp_async16(sa + dof, Ag + kof + ch*8);                               \
            cp_async16(sb + dof, Wg + kof + ch*8);                               \
        }                                                                        \
    } while (0)

    G_LOAD(0, 0); cp_commit();
    G_LOAD(1, 1); cp_commit();

    for (int s = 0; s < G_NSTEP; s++) {
        cp_wait1();
        __syncthreads();
        if (s + 2 < G_NSTEP) { G_LOAD(s + 2, (s + 2) % G_STAGES); }
        cp_commit();

        const uint32_t A_sa = asb + (s % G_STAGES) * G_TBY;
        const uint32_t B_sa = bsb + (s % G_STAGES) * G_TBY;

        #pragma unroll
        for (int ks = 0; ks < 4; ks++) {
            const uint32_t ka  = (uint32_t)(2*ks + a_ksel);
            const uint32_t kb_ = (uint32_t)(2*ks + b_ksel);
            uint32_t af[4][4], bf[2][4];
            #pragma unroll
            for (int mi = 0; mi < 4; mi++)
                ldsm_x4(af[mi], A_sa + a_off[mi] + ((ka ^ a_sw[mi]) << 4));
            #pragma unroll
            for (int pi = 0; pi < 2; pi++)
                ldsm_x4(bf[pi], B_sa + b_off[pi] + ((kb_ ^ b_sw[pi]) << 4));
            #pragma unroll
            for (int mi = 0; mi < 4; mi++)
                #pragma unroll
                for (int ni = 0; ni < 4; ni++)
                    mma_f16(acc[mi][ni], af[mi], &bf[ni >> 1][(ni & 1) * 2]);
        }
    }
    #undef G_LOAD
    __syncthreads();

    #pragma unroll
    for (int mi = 0; mi < 4; mi++) {
        const int r0 = m0 + wm + mi*16 + fr;
        #pragma unroll
        for (int ni = 0; ni < 4; ni++) {
            const int col = n0 + wn + ni*8 + fc*2;
            if (HALF_OUT) {
                *(__half2*)(Ch + (size_t)r0       * Cc + col) =
                    __floats2half2_rn(acc[mi][ni][0], acc[mi][ni][1]);
                *(__half2*)(Ch + (size_t)(r0 + 8) * Cc + col) =
                    __floats2half2_rn(acc[mi][ni][2], acc[mi][ni][3]);
            } else {
                const float b0 = __ldg(bias + col), b1 = __ldg(bias + col + 1);
                *(float2*)(Cf + (size_t)r0       * Cc + col) =
                    make_float2(acc[mi][ni][0] + b0, acc[mi][ni][1] + b1);
                *(float2*)(Cf + (size_t)(r0 + 8) * Cc + col) =
                    make_float2(acc[mi][ni][2] + b0, acc[mi][ni][3] + b1);
            }
        }
    }
}

__global__ void __launch_bounds__(256, 2)
gemm_out(const __half* __restrict__ A, const __half* __restrict__ W,
         const float* __restrict__ bias, float* __restrict__ C) {
    gemm_body<false>(A, W, bias, C, nullptr);
}

__global__ void __launch_bounds__(256, 2)
gemm_qkv(const __half* __restrict__ A,
         const __half* __restrict__ W0, const __half* __restrict__ W1,
         const __half* __restrict__ W2,
         __half* __restrict__ C0, __half* __restrict__ C1, __half* __restrict__ C2) {
    const __half* W = (blockIdx.z == 0) ? W0 : (blockIdx.z == 1) ? W1 : W2;
    __half*       C = (blockIdx.z == 0) ? C0 : (blockIdx.z == 1) ? C1 : C2;
    gemm_body<true>(A, W, nullptr, nullptr, C);
}

// ===========================================================================
// Flash-attention, fp16 mma.sync, double-buffered K/V (R10 structure).
// CTA = 128 threads, one (b,h,64-query tile). smem 88KB -> 2 CTAs/SM.
// Scale*log2e folded into Wq; softmax uses raw ex2.
// ===========================================================================
#define AT_Q  0
#define AT_K0 16384
#define AT_V0 49152
#define AT_P  81920
#define AT_SMEM 90112

__global__ void __launch_bounds__(128, 2) attn_f16(const int* __restrict__ pm)
{
    extern __shared__ char smc[];
    const uint32_t sb  = smem_u32(smc);
    const uint32_t qsb = sb + AT_Q;
    const uint32_t psb = sb + AT_P;

    const int qb = (gridDim.x - 1) - blockIdx.x;   // descending order
    const int h  = blockIdx.y;
    const int b  = blockIdx.z;
    const int tid  = threadIdx.x;
    const int lane = tid & 31;
    const int warp = tid >> 5;
    const int fr = lane >> 2;
    const int fc = lane & 3;

    const int a_msel = (lane >> 3) & 1;
    const int a_ksel = lane >> 4;
    const int b_nsel = (lane >> 4) & 1;
    const int b_ksel = (lane >> 3) & 1;
    const int v_ssel = (lane >> 3) & 1;
    const int v_dsel = (lane >> 4) & 1;
    const int a_row  = warp*16 + a_msel*8 + (lane & 7);

    const size_t hoff = (size_t)h * Dd;
    const __half* Qg = g_qh + (size_t)b * Tt * Cc + hoff;
    const __half* Kg = g_kh + (size_t)b * Tt * Cc + hoff;
    const __half* Vg = g_vh + (size_t)b * Tt * Cc + hoff;
    const int q0 = qb * 64;

    const int lrow = tid >> 1;
    const int lch0 = (tid & 1) * 8;
    const uint32_t lsw = (uint32_t)(lrow & 7);

    #define AT_LOADKV(kt, st) do {                                                 \
        const uint32_t kb_ = sb + AT_K0 + (st)*16384;                              \
        const uint32_t vb_ = sb + AT_V0 + (st)*16384;                              \
        _Pragma("unroll")                                                          \
        for (int j = 0; j < 8; j++) {                                              \
            const int ch = lch0 + j;                                               \
            const uint32_t doff = lrow*256 + (((uint32_t)ch ^ lsw) << 4);          \
            cp_async16(kb_ + doff, Kg + (size_t)((kt)*64 + lrow)*Cc + ch*8);       \
            cp_async16(vb_ + doff, Vg + (size_t)((kt)*64 + lrow)*Cc + ch*8);       \
        }                                                                          \
        cp_commit();                                                               \
    } while (0)

    #pragma unroll
    for (int j = 0; j < 8; j++) {
        const int ch = lch0 + j;
        cp_async16(qsb + lrow*256 + (((uint32_t)ch ^ lsw) << 4),
                   Qg + (size_t)(q0 + lrow)*Cc + ch*8);
    }
    cp_commit();
    AT_LOADKV(0, 0);
    cp_wait1();
    __syncthreads();

    uint32_t qf[8][4];
    #pragma unroll
    for (int kb = 0; kb < 8; kb++)
        ldsm_x4(qf[kb], qsb + a_row*256 + (((uint32_t)(2*kb + a_ksel) ^ (uint32_t)(a_row & 7)) << 4));

    const int rowA = q0 + warp*16 + fr;
    const int rowB = rowA + 8;
    const int pmA = pm[b*Tt + rowA];
    const int pmB = pm[b*Tt + rowB];
    const int prA = warp*16 + fr;

    float o[16][4];
    #pragma unroll
    for (int i = 0; i < 16; i++)
        #pragma unroll
        for (int j = 0; j < 4; j++) o[i][j] = 0.f;
    float mA = -INFINITY, mB = -INFINITY, lA = 0.f, lB = 0.f;

    for (int kt = 0; kt <= qb; kt++) {
        const int cur = kt & 1;
        const bool more = (kt + 1 <= qb);
        if (more) AT_LOADKV(kt + 1, cur ^ 1);
        if (more) cp_wait1(); else cp_wait0();
        __syncthreads();

        const uint32_t ksb = sb + AT_K0 + cur*16384;
        const uint32_t vsb = sb + AT_V0 + cur*16384;

        // ---- S = Q K^T (scale*log2e pre-folded into q) ----
        float sa[8][4];
        #pragma unroll
        for (int ni = 0; ni < 8; ni++)
            #pragma unroll
            for (int j = 0; j < 4; j++) sa[ni][j] = 0.f;

        #pragma unroll
        for (int kb = 0; kb < 8; kb++) {
            uint32_t bq[4][4];
            #pragma unroll
            for (int pi = 0; pi < 4; pi++) {
                const int n = pi*16 + b_nsel*8 + (lane & 7);
                ldsm_x4(bq[pi], ksb + n*256 + (((uint32_t)(2*kb + b_ksel) ^ (uint32_t)(n & 7)) << 4));
            }
            #pragma unroll
            for (int ni = 0; ni < 8; ni++)
                mma_f16(sa[ni], qf[kb], &bq[ni >> 1][(ni & 1) * 2]);
        }

        // ---- mask + online softmax (base-2 domain) ----
        float mxA = -INFINITY, mxB = -INFINITY;
        #pragma unroll
        for (int ni = 0; ni < 8; ni++) {
            const int c0 = kt*64 + ni*8 + 2*fc;
            float s0 = sa[ni][0], s1 = sa[ni][1];
            float s2 = sa[ni][2], s3 = sa[ni][3];
            if (pmA == 0) { s0 = -1e9f; s1 = -1e9f; }
            if (pmB == 0) { s2 = -1e9f; s3 = -1e9f; }
            if (kt == qb) {
                if (c0     > rowA) s0 = -INFINITY;
                if (c0 + 1 > rowA) s1 = -INFINITY;
                if (c0     > rowB) s2 = -INFINITY;
                if (c0 + 1 > rowB) s3 = -INFINITY;
            }
            sa[ni][0] = s0; sa[ni][1] = s1; sa[ni][2] = s2; sa[ni][3] = s3;
            mxA = fmaxf(mxA, fmaxf(s0, s1));
            mxB = fmaxf(mxB, fmaxf(s2, s3));
        }
        mxA = fmaxf(mxA, __shfl_xor_sync(0xffffffffu, mxA, 1));
        mxA = fmaxf(mxA, __shfl_xor_sync(0xffffffffu, mxA, 2));
        mxB = fmaxf(mxB, __shfl_xor_sync(0xffffffffu, mxB, 1));
        mxB = fmaxf(mxB, __shfl_xor_sync(0xffffffffu, mxB, 2));

        const float mnA = fmaxf(mA, mxA), mnB = fmaxf(mB, mxB);
        const float sfA = exp2a(mA - mnA), sfB = exp2a(mB - mnB);
        mA = mnA; mB = mnB;

        float suA = 0.f, suB = 0.f;
        #pragma unroll
        for (int ni = 0; ni < 8; ni++) {
            __half2 h01 = __floats2half2_rn(exp2a(sa[ni][0] - mA), exp2a(sa[ni][1] - mA));
            __half2 h23 = __floats2half2_rn(exp2a(sa[ni][2] - mB), exp2a(sa[ni][3] - mB));
            const float2 f01 = __half22float2(h01);
            const float2 f23 = __half22float2(h23);
            suA += f01.x + f01.y; suB += f23.x + f23.y;
            const uint32_t aoA = psb + prA*128     + (((uint32_t)ni ^ (uint32_t)(prA & 7))     << 4) + fc*4;
            const uint32_t aoB = psb + (prA+8)*128 + (((uint32_t)ni ^ (uint32_t)((prA+8) & 7)) << 4) + fc*4;
            *(__half2*)(smc + (aoA - sb)) = h01;
            *(__half2*)(smc + (aoB - sb)) = h23;
        }
        suA += __shfl_xor_sync(0xffffffffu, suA, 1);
        suA += __shfl_xor_sync(0xffffffffu, suA, 2);
        suB += __shfl_xor_sync(0xffffffffu, suB, 1);
        suB += __shfl_xor_sync(0xffffffffu, suB, 2);
        lA = lA*sfA + suA;
        lB = lB*sfB + suB;
        #pragma unroll
        for (int ni = 0; ni < 16; ni++) {
            o[ni][0] *= sfA; o[ni][1] *= sfA;
            o[ni][2] *= sfB; o[ni][3] *= sfB;
        }
        __syncwarp();

        #pragma unroll
        for (int kb = 0; kb < 4; kb++) {
            uint32_t pa[4];
            ldsm_x4(pa, psb + a_row*128 + (((uint32_t)(2*kb + a_ksel) ^ (uint32_t)(a_row & 7)) << 4));
            #pragma unroll
            for (int di = 0; di < 8; di++) {
                uint32_t bv[4];
                const int sv = kb*16 + v_ssel*8 + (lane & 7);
                const uint32_t ch = (uint32_t)(2*di + v_dsel);
                ldsm_x4_t(bv, vsb + sv*256 + ((ch ^ (uint32_t)(sv & 7)) << 4));
                mma_f16(o[di*2    ], pa, &bv[0]);
                mma_f16(o[di*2 + 1], pa, &bv[2]);
            }
        }
        __syncthreads();
    }
    #undef AT_LOADKV

    const float iA = 1.f / lA, iB = 1.f / lB;
    __half* cpA = g_ctxh + (size_t)(b*Tt + rowA)*Cc + hoff;
    __half* cpB = g_ctxh + (size_t)(b*Tt + rowB)*Cc + hoff;
    #pragma unroll
    for (int ni = 0; ni < 16; ni++) {
        const int d0 = ni*8 + 2*fc;
        *(__half2*)(cpA + d0) = __floats2half2_rn(o[ni][0]*iA, o[ni][1]*iA);
        *(__half2*)(cpB + d0) = __floats2half2_rn(o[ni][2]*iB, o[ni][3]*iB);
    }
}

// ===========================================================================
extern "C" void kernel_launch(void* const* d_in, const int* in_sizes, int n_in,
                              void* d_out, int out_size)
{
    (void)in_sizes; (void)n_in; (void)out_size;
    const float* x  = (const float*)d_in[0];
    const int*   pm = (const int*)  d_in[1];
    const float* Wq = (const float*)d_in[2];
    const float* Wk = (const float*)d_in[3];
    const float* Wv = (const float*)d_in[4];
    const float* Wp = (const float*)d_in[5];
    const float* bp = (const float*)d_in[6];
    float* out = (float*)d_out;

    __half *xh, *wqh, *wkh, *wvh, *wph, *qh, *kh, *vh, *ctxh;
    cudaGetSymbolAddress((void**)&xh,   g_xh);
    cudaGetSymbolAddress((void**)&wqh,  g_wqh);
    cudaGetSymbolAddress((void**)&wkh,  g_wkh);
    cudaGetSymbolAddress((void**)&wvh,  g_wvh);
    cudaGetSymbolAddress((void**)&wph,  g_wph);
    cudaGetSymbolAddress((void**)&qh,   g_qh);
    cudaGetSymbolAddress((void**)&kh,   g_kh);
    cudaGetSymbolAddress((void**)&vh,   g_vh);
    cudaGetSymbolAddress((void**)&ctxh, g_ctxh);

    const int nb = (NTOK*Cc/4 + 255) / 256;
    tohalf_all<<<dim3(nb, 1, 5), 256>>>(
        (const float4*)x,  xh,
        (const float4*)Wq, wqh,
        (const float4*)Wk, wkh,
        (const float4*)Wv, wvh,
        (const float4*)Wp, wph);

    cudaFuncSetAttribute(gemm_qkv, cudaFuncAttributeMaxDynamicSharedMemorySize, G_SMEM);
    cudaFuncSetAttribute(gemm_out, cudaFuncAttributeMaxDynamicSharedMemorySize, G_SMEM);
    cudaFuncSetAttribute(attn_f16, cudaFuncAttributeMaxDynamicSharedMemorySize, AT_SMEM);

    gemm_qkv<<<dim3(Cc/128, NTOK/128, 3), 256, G_SMEM>>>(xh, wqh, wkh, wvh, qh, kh, vh);
    attn_f16<<<dim3(Tt/64, Hh, Bb), 128, AT_SMEM>>>(pm);
    gemm_out<<<dim3(Cc/128, NTOK/128), 256, G_SMEM>>>(ctxh, wph, bp, out);
}

// round 13
// speedup vs baseline: 1.0332x; 1.0038x over previous
#include <cuda_runtime.h>
#include <cuda_fp16.h>
#include <cstdint>
#include <math.h>

#define Bb 2
#define Tt 2048
#define Cc 2048
#define Hh 16
#define Dd 128
#define NTOK (Bb*Tt)   // 4096

// Scratch (device globals: no runtime allocation allowed)
__device__ __half g_xh [(size_t)NTOK*Cc];
__device__ __half g_wqh[(size_t)Cc*Cc];
__device__ __half g_wkh[(size_t)Cc*Cc];
__device__ __half g_wvh[(size_t)Cc*Cc];
__device__ __half g_wph[(size_t)Cc*Cc];
__device__ __half g_qh [(size_t)NTOK*Cc];
__device__ __half g_kh [(size_t)NTOK*Cc];
__device__ __half g_vh [(size_t)NTOK*Cc];
__device__ __half g_ctxh[(size_t)NTOK*Cc];

// ===========================================================================
// helpers
// ===========================================================================
__device__ __forceinline__ uint32_t smem_u32(const void* p) {
    uint32_t a;
    asm("{ .reg .u64 t; cvta.to.shared.u64 t, %1; cvt.u32.u64 %0, t; }" : "=r"(a) : "l"(p));
    return a;
}
__device__ __forceinline__ void cp_async16(uint32_t dst, const void* src) {
    asm volatile("cp.async.cg.shared.global [%0], [%1], 16;" :: "r"(dst), "l"(src) : "memory");
}
__device__ __forceinline__ void cp_commit() {
    asm volatile("cp.async.commit_group;" ::: "memory");
}
__device__ __forceinline__ void cp_wait1() {
    asm volatile("cp.async.wait_group 1;" ::: "memory");
}
__device__ __forceinline__ void cp_wait0() {
    asm volatile("cp.async.wait_group 0;" ::: "memory");
}
__device__ __forceinline__ void ldsm_x4(uint32_t* r, uint32_t addr) {
    asm volatile("ldmatrix.sync.aligned.m8n8.x4.shared.b16 {%0,%1,%2,%3}, [%4];"
                 : "=r"(r[0]), "=r"(r[1]), "=r"(r[2]), "=r"(r[3]) : "r"(addr));
}
__device__ __forceinline__ void ldsm_x4_t(uint32_t* r, uint32_t addr) {
    asm volatile("ldmatrix.sync.aligned.m8n8.x4.trans.shared.b16 {%0,%1,%2,%3}, [%4];"
                 : "=r"(r[0]), "=r"(r[1]), "=r"(r[2]), "=r"(r[3]) : "r"(addr));
}
// m16n8k16 fp16 MMA, fp32 accumulate
__device__ __forceinline__ void mma_f16(float* c, const uint32_t* a, const uint32_t* b) {
    asm volatile(
        "mma.sync.aligned.m16n8k16.row.col.f32.f16.f16.f32 "
        "{%0,%1,%2,%3}, {%4,%5,%6,%7}, {%8,%9}, {%0,%1,%2,%3};"
        : "+f"(c[0]), "+f"(c[1]), "+f"(c[2]), "+f"(c[3])
        : "r"(a[0]), "r"(a[1]), "r"(a[2]), "r"(a[3]), "r"(b[0]), "r"(b[1]));
}
// raw MUFU ex2 (exp base 2); log2e folded into Wq so no multiply needed
__device__ __forceinline__ float exp2a(float x) {
    float y;
    asm("ex2.approx.f32 %0, %1;" : "=f"(y) : "f"(x));
    return y;
}

// ===========================================================================
// fp32 -> fp16 conversion; Wq gets (1/sqrt(D)) * log2(e) folded in
// ===========================================================================
__global__ void __launch_bounds__(256) tohalf_all(
    const float4* __restrict__ x,  __half* __restrict__ xr,
    const float4* __restrict__ w0, __half* __restrict__ r0,
    const float4* __restrict__ w1, __half* __restrict__ r1,
    const float4* __restrict__ w2, __half* __restrict__ r2,
    const float4* __restrict__ w3, __half* __restrict__ r3)
{
    const int z = blockIdx.z;
    const float4* src; __half* dst; int n4;
    float sc = 1.0f;
    if      (z == 0) { src = x;  dst = xr; n4 = NTOK*Cc/4; }
    else if (z == 1) { src = w0; dst = r0; n4 = Cc*Cc/4;
                       sc = 0.08838834764831845f * 1.4426950408889634f; }
    else if (z == 2) { src = w1; dst = r1; n4 = Cc*Cc/4; }
    else if (z == 3) { src = w2; dst = r2; n4 = Cc*Cc/4; }
    else             { src = w3; dst = r3; n4 = Cc*Cc/4; }
    int i = blockIdx.x * blockDim.x + threadIdx.x;
    if (i < n4) {
        float4 v = src[i];
        *(__half2*)(dst + (size_t)i*4)     = __floats2half2_rn(v.x*sc, v.y*sc);
        *(__half2*)(dst + (size_t)i*4 + 2) = __floats2half2_rn(v.z*sc, v.w*sc);
    }
}

// ===========================================================================
// fp16 mma.sync GEMM (unchanged): CTA 128x128, 256 thr, BK=64, 3 stages,
// 96KB smem -> 2 CTAs/SM.
// ===========================================================================
#define G_BK     64
#define G_TBY    (128*128)
#define G_STAGES 3
#define G_SMEM   (G_STAGES*2*G_TBY)            // 98304
#define G_NSTEP  (Cc / G_BK)                   // 32

template<bool HALF_OUT>
__device__ __forceinline__ void gemm_body(const __half* __restrict__ A,
                                          const __half* __restrict__ W,
                                          const float* __restrict__ bias,
                                          float* __restrict__ Cf,
                                          __half* __restrict__ Ch)
{
    extern __shared__ char smc[];
    const uint32_t asb = smem_u32(smc);
    const uint32_t bsb = asb + G_STAGES * G_TBY;

    const int tid  = threadIdx.x;
    const int lane = tid & 31;
    const int warp = tid >> 5;
    const int n0 = blockIdx.x * 128;
    const int m0 = blockIdx.y * 128;
    const int wm = (warp & 1) * 64;
    const int wn = (warp >> 1) * 32;
    const int fr = lane >> 2;
    const int fc = lane & 3;

    const int a_msel = (lane >> 3) & 1;
    const int a_ksel = lane >> 4;
    const int b_nsel = (lane >> 4) & 1;
    const int b_ksel = (lane >> 3) & 1;
    uint32_t a_off[4], a_sw[4], b_off[2], b_sw[2];
    #pragma unroll
    for (int mi = 0; mi < 4; mi++) {
        const int r = wm + mi*16 + a_msel*8 + (lane & 7);
        a_off[mi] = (uint32_t)r * 128;
        a_sw[mi]  = (uint32_t)(r & 7);
    }
    #pragma unroll
    for (int pi = 0; pi < 2; pi++) {
        const int n = wn + pi*16 + b_nsel*8 + (lane & 7);
        b_off[pi] = (uint32_t)n * 128;
        b_sw[pi]  = (uint32_t)(n & 7);
    }

    const int lr  = tid >> 1;
    const int lj0 = (tid & 1) * 4;
    const __half* Ag = A + (size_t)(m0 + lr) * Cc;
    const __half* Wg = W + (size_t)(n0 + lr) * Cc;
    const uint32_t swr = (uint32_t)(lr & 7);

    float acc[4][4][4];
    #pragma unroll
    for (int i = 0; i < 4; i++)
        #pragma unroll
        for (int j = 0; j < 4; j++)
            #pragma unroll
            for (int q = 0; q < 4; q++) acc[i][j][q] = 0.f;

    #define G_LOAD(s, st) do {                                                  \
        const uint32_t sa = asb + (st) * G_TBY;                                  \
        const uint32_t sb = bsb + (st) * G_TBY;                                  \
        const int kof = (s) * G_BK;                                              \
        _Pragma("unroll")                                                        \
        for (int j = 0; j < 4; j++) {                                            \
            const int ch = lj0 + j;                                              \
            const uint32_t dof = lr*128 + (((uint32_t)ch ^ swr) << 4);           \
            cp_async16(sa + dof, Ag + kof + ch*8);                               \
            cp_async16(sb + dof, Wg + kof + ch*8);                               \
        }                                                                        \
    } while (0)

    G_LOAD(0, 0); cp_commit();
    G_LOAD(1, 1); cp_commit();

    for (int s = 0; s < G_NSTEP; s++) {
        cp_wait1();
        __syncthreads();
        if (s + 2 < G_NSTEP) { G_LOAD(s + 2, (s + 2) % G_STAGES); }
        cp_commit();

        const uint32_t A_sa = asb + (s % G_STAGES) * G_TBY;
        const uint32_t B_sa = bsb + (s % G_STAGES) * G_TBY;

        #pragma unroll
        for (int ks = 0; ks < 4; ks++) {
            const uint32_t ka  = (uint32_t)(2*ks + a_ksel);
            const uint32_t kb_ = (uint32_t)(2*ks + b_ksel);
            uint32_t af[4][4], bf[2][4];
            #pragma unroll
            for (int mi = 0; mi < 4; mi++)
                ldsm_x4(af[mi], A_sa + a_off[mi] + ((ka ^ a_sw[mi]) << 4));
            #pragma unroll
            for (int pi = 0; pi < 2; pi++)
                ldsm_x4(bf[pi], B_sa + b_off[pi] + ((kb_ ^ b_sw[pi]) << 4));
            #pragma unroll
            for (int mi = 0; mi < 4; mi++)
                #pragma unroll
                for (int ni = 0; ni < 4; ni++)
                    mma_f16(acc[mi][ni], af[mi], &bf[ni >> 1][(ni & 1) * 2]);
        }
    }
    #undef G_LOAD
    __syncthreads();

    #pragma unroll
    for (int mi = 0; mi < 4; mi++) {
        const int r0 = m0 + wm + mi*16 + fr;
        #pragma unroll
        for (int ni = 0; ni < 4; ni++) {
            const int col = n0 + wn + ni*8 + fc*2;
            if (HALF_OUT) {
                *(__half2*)(Ch + (size_t)r0       * Cc + col) =
                    __floats2half2_rn(acc[mi][ni][0], acc[mi][ni][1]);
                *(__half2*)(Ch + (size_t)(r0 + 8) * Cc + col) =
                    __floats2half2_rn(acc[mi][ni][2], acc[mi][ni][3]);
            } else {
                const float b0 = __ldg(bias + col), b1 = __ldg(bias + col + 1);
                *(float2*)(Cf + (size_t)r0       * Cc + col) =
                    make_float2(acc[mi][ni][0] + b0, acc[mi][ni][1] + b1);
                *(float2*)(Cf + (size_t)(r0 + 8) * Cc + col) =
                    make_float2(acc[mi][ni][2] + b0, acc[mi][ni][3] + b1);
            }
        }
    }
}

__global__ void __launch_bounds__(256, 2)
gemm_out(const __half* __restrict__ A, const __half* __restrict__ W,
         const float* __restrict__ bias, float* __restrict__ C) {
    gemm_body<false>(A, W, bias, C, nullptr);
}

__global__ void __launch_bounds__(256, 2)
gemm_qkv(const __half* __restrict__ A,
         const __half* __restrict__ W0, const __half* __restrict__ W1,
         const __half* __restrict__ W2,
         __half* __restrict__ C0, __half* __restrict__ C1, __half* __restrict__ C2) {
    const __half* W = (blockIdx.z == 0) ? W0 : (blockIdx.z == 1) ? W1 : W2;
    __half*       C = (blockIdx.z == 0) ? C0 : (blockIdx.z == 1) ? C1 : C2;
    gemm_body<true>(A, W, nullptr, nullptr, C);
}

// ===========================================================================
// Flash-attention, fp16 mma.sync, double-buffered K/V (R10 structure).
// CTA = 128 threads, one (b,h,64-query tile). smem 88KB -> 2 CTAs/SM.
// Scale*log2e folded into Wq; softmax uses raw ex2.
// ===========================================================================
#define AT_Q  0
#define AT_K0 16384
#define AT_V0 49152
#define AT_P  81920
#define AT_SMEM 90112

__global__ void __launch_bounds__(128, 2) attn_f16(const int* __restrict__ pm)
{
    extern __shared__ char smc[];
    const uint32_t sb  = smem_u32(smc);
    const uint32_t qsb = sb + AT_Q;
    const uint32_t psb = sb + AT_P;

    const int qb = (gridDim.x - 1) - blockIdx.x;   // descending order
    const int h  = blockIdx.y;
    const int b  = blockIdx.z;
    const int tid  = threadIdx.x;
    const int lane = tid & 31;
    const int warp = tid >> 5;
    const int fr = lane >> 2;
    const int fc = lane & 3;

    const int a_msel = (lane >> 3) & 1;
    const int a_ksel = lane >> 4;
    const int b_nsel = (lane >> 4) & 1;
    const int b_ksel = (lane >> 3) & 1;
    const int v_ssel = (lane >> 3) & 1;
    const int v_dsel = (lane >> 4) & 1;
    const int a_row  = warp*16 + a_msel*8 + (lane & 7);

    const size_t hoff = (size_t)h * Dd;
    const __half* Qg = g_qh + (size_t)b * Tt * Cc + hoff;
    const __half* Kg = g_kh + (size_t)b * Tt * Cc + hoff;
    const __half* Vg = g_vh + (size_t)b * Tt * Cc + hoff;
    const int q0 = qb * 64;

    const int lrow = tid >> 1;
    const int lch0 = (tid & 1) * 8;
    const uint32_t lsw = (uint32_t)(lrow & 7);

    #define AT_LOADKV(kt, st) do {                                                 \
        const uint32_t kb_ = sb + AT_K0 + (st)*16384;                              \
        const uint32_t vb_ = sb + AT_V0 + (st)*16384;                              \
        _Pragma("unroll")                                                          \
        for (int j = 0; j < 8; j++) {                                              \
            const int ch = lch0 + j;                                               \
            const uint32_t doff = lrow*256 + (((uint32_t)ch ^ lsw) << 4);          \
            cp_async16(kb_ + doff, Kg + (size_t)((kt)*64 + lrow)*Cc + ch*8);       \
            cp_async16(vb_ + doff, Vg + (size_t)((kt)*64 + lrow)*Cc + ch*8);       \
        }                                                                          \
        cp_commit();                                                               \
    } while (0)

    #pragma unroll
    for (int j = 0; j < 8; j++) {
        const int ch = lch0 + j;
        cp_async16(qsb + lrow*256 + (((uint32_t)ch ^ lsw) << 4),
                   Qg + (size_t)(q0 + lrow)*Cc + ch*8);
    }
    cp_commit();
    AT_LOADKV(0, 0);
    cp_wait1();
    __syncthreads();

    uint32_t qf[8][4];
    #pragma unroll
    for (int kb = 0; kb < 8; kb++)
        ldsm_x4(qf[kb], qsb + a_row*256 + (((uint32_t)(2*kb + a_ksel) ^ (uint32_t)(a_row & 7)) << 4));

    const int rowA = q0 + warp*16 + fr;
    const int rowB = rowA + 8;
    const int pmA = pm[b*Tt + rowA];
    const int pmB = pm[b*Tt + rowB];
    const int prA = warp*16 + fr;

    float o[16][4];
    #pragma unroll
    for (int i = 0; i < 16; i++)
        #pragma unroll
        for (int j = 0; j < 4; j++) o[i][j] = 0.f;
    float mA = -INFINITY, mB = -INFINITY, lA = 0.f, lB = 0.f;

    for (int kt = 0; kt <= qb; kt++) {
        const int cur = kt & 1;
        const bool more = (kt + 1 <= qb);
        if (more) AT_LOADKV(kt + 1, cur ^ 1);
        if (more) cp_wait1(); else cp_wait0();
        __syncthreads();

        const uint32_t ksb = sb + AT_K0 + cur*16384;
        const uint32_t vsb = sb + AT_V0 + cur*16384;

        // ---- S = Q K^T (scale*log2e pre-folded into q) ----
        float sa[8][4];
        #pragma unroll
        for (int ni = 0; ni < 8; ni++)
            #pragma unroll
            for (int j = 0; j < 4; j++) sa[ni][j] = 0.f;

        #pragma unroll
        for (int kb = 0; kb < 8; kb++) {
            uint32_t bq[4][4];
            #pragma unroll
            for (int pi = 0; pi < 4; pi++) {
                const int n = pi*16 + b_nsel*8 + (lane & 7);
                ldsm_x4(bq[pi], ksb + n*256 + (((uint32_t)(2*kb + b_ksel) ^ (uint32_t)(n & 7)) << 4));
            }
            #pragma unroll
            for (int ni = 0; ni < 8; ni++)
                mma_f16(sa[ni], qf[kb], &bq[ni >> 1][(ni & 1) * 2]);
        }

        // ---- mask + online softmax (base-2 domain) ----
        float mxA = -INFINITY, mxB = -INFINITY;
        #pragma unroll
        for (int ni = 0; ni < 8; ni++) {
            const int c0 = kt*64 + ni*8 + 2*fc;
            float s0 = sa[ni][0], s1 = sa[ni][1];
            float s2 = sa[ni][2], s3 = sa[ni][3];
            if (pmA == 0) { s0 = -1e9f; s1 = -1e9f; }
            if (pmB == 0) { s2 = -1e9f; s3 = -1e9f; }
            if (kt == qb) {
                if (c0     > rowA) s0 = -INFINITY;
                if (c0 + 1 > rowA) s1 = -INFINITY;
                if (c0     > rowB) s2 = -INFINITY;
                if (c0 + 1 > rowB) s3 = -INFINITY;
            }
            sa[ni][0] = s0; sa[ni][1] = s1; sa[ni][2] = s2; sa[ni][3] = s3;
            mxA = fmaxf(mxA, fmaxf(s0, s1));
            mxB = fmaxf(mxB, fmaxf(s2, s3));
        }
        mxA = fmaxf(mxA, __shfl_xor_sync(0xffffffffu, mxA, 1));
        mxA = fmaxf(mxA, __shfl_xor_sync(0xffffffffu, mxA, 2));
        mxB = fmaxf(mxB, __shfl_xor_sync(0xffffffffu, mxB, 1));
        mxB = fmaxf(mxB, __shfl_xor_sync(0xffffffffu, mxB, 2));

        const float mnA = fmaxf(mA, mxA), mnB = fmaxf(mB, mxB);
        const float sfA = exp2a(mA - mnA), sfB = exp2a(mB - mnB);
        mA = mnA; mB = mnB;

        float suA = 0.f, suB = 0.f;
        #pragma unroll
        for (int ni = 0; ni < 8; ni++) {
            __half2 h01 = __floats2half2_rn(exp2a(sa[ni][0] - mA), exp2a(sa[ni][1] - mA));
            __half2 h23 = __floats2half2_rn(exp2a(sa[ni][2] - mB), exp2a(sa[ni][3] - mB));
            const float2 f01 = __half22float2(h01);
            const float2 f23 = __half22float2(h23);
            suA += f01.x + f01.y; suB += f23.x + f23.y;
            const uint32_t aoA = psb + prA*128     + (((uint32_t)ni ^ (uint32_t)(prA & 7))     << 4) + fc*4;
            const uint32_t aoB = psb + (prA+8)*128 + (((uint32_t)ni ^ (uint32_t)((prA+8) & 7)) << 4) + fc*4;
            *(__half2*)(smc + (aoA - sb)) = h01;
            *(__half2*)(smc + (aoB - sb)) = h23;
        }
        suA += __shfl_xor_sync(0xffffffffu, suA, 1);
        suA += __shfl_xor_sync(0xffffffffu, suA, 2);
        suB += __shfl_xor_sync(0xffffffffu, suB, 1);
        suB += __shfl_xor_sync(0xffffffffu, suB, 2);
        lA = lA*sfA + suA;
        lB = lB*sfB + suB;
        #pragma unroll
        for (int ni = 0; ni < 16; ni++) {
            o[ni][0] *= sfA; o[ni][1] *= sfA;
            o[ni][2] *= sfB; o[ni][3] *= sfB;
        }
        __syncwarp();

        #pragma unroll
        for (int kb = 0; kb < 4; kb++) {
            uint32_t pa[4];
            ldsm_x4(pa, psb + a_row*128 + (((uint32_t)(2*kb + a_ksel) ^ (uint32_t)(a_row & 7)) << 4));
            #pragma unroll
            for (int di = 0; di < 8; di++) {
                uint32_t bv[4];
                const int sv = kb*16 + v_ssel*8 + (lane & 7);
                const uint32_t ch = (uint32_t)(2*di + v_dsel);
                ldsm_x4_t(bv, vsb + sv*256 + ((ch ^ (uint32_t)(sv & 7)) << 4));
                mma_f16(o[di*2    ], pa, &bv[0]);
                mma_f16(o[di*2 + 1], pa, &bv[2]);
            }
        }
        __syncthreads();
    }
    #undef AT_LOADKV

    const float iA = 1.f / lA, iB = 1.f / lB;
    __half* cpA = g_ctxh + (size_t)(b*Tt + rowA)*Cc + hoff;
    __half* cpB = g_ctxh + (size_t)(b*Tt + rowB)*Cc + hoff;
    #pragma unroll
    for (int ni = 0; ni < 16; ni++) {
        const int d0 = ni*8 + 2*fc;
        *(__half2*)(cpA + d0) = __floats2half2_rn(o[ni][0]*iA, o[ni][1]*iA);
        *(__half2*)(cpB + d0) = __floats2half2_rn(o[ni][2]*iB, o[ni][3]*iB);
    }
}

// ===========================================================================
extern "C" void kernel_launch(void* const* d_in, const int* in_sizes, int n_in,
                              void* d_out, int out_size)
{
    (void)in_sizes; (void)n_in; (void)out_size;
    const float* x  = (const float*)d_in[0];
    const int*   pm = (const int*)  d_in[1];
    const float* Wq = (const float*)d_in[2];
    const float* Wk = (const float*)d_in[3];
    const float* Wv = (const float*)d_in[4];
    const float* Wp = (const float*)d_in[5];
    const float* bp = (const float*)d_in[6];
    float* out = (float*)d_out;

    __half *xh, *wqh, *wkh, *wvh, *wph, *qh, *kh, *vh, *ctxh;
    cudaGetSymbolAddress((void**)&xh,   g_xh);
    cudaGetSymbolAddress((void**)&wqh,  g_wqh);
    cudaGetSymbolAddress((void**)&wkh,  g_wkh);
    cudaGetSymbolAddress((void**)&wvh,  g_wvh);
    cudaGetSymbolAddress((void**)&wph,  g_wph);
    cudaGetSymbolAddress((void**)&qh,   g_qh);
    cudaGetSymbolAddress((void**)&kh,   g_kh);
    cudaGetSymbolAddress((void**)&vh,   g_vh);
    cudaGetSymbolAddress((void**)&ctxh, g_ctxh);

    const int nb = (NTOK*Cc/4 + 255) / 256;
    tohalf_all<<<dim3(nb, 1, 5), 256>>>(
        (const float4*)x,  xh,
        (const float4*)Wq, wqh,
        (const float4*)Wk, wkh,
        (const float4*)Wv, wvh,
        (const float4*)Wp, wph);

    cudaFuncSetAttribute(gemm_qkv, cudaFuncAttributeMaxDynamicSharedMemorySize, G_SMEM);
    cudaFuncSetAttribute(gemm_out, cudaFuncAttributeMaxDynamicSharedMemorySize, G_SMEM);
    cudaFuncSetAttribute(attn_f16, cudaFuncAttributeMaxDynamicSharedMemorySize, AT_SMEM);

    gemm_qkv<<<dim3(Cc/128, NTOK/128, 3), 256, G_SMEM>>>(xh, wqh, wkh, wvh, qh, kh, vh);
    attn_f16<<<dim3(Tt/64, Hh, Bb), 128, AT_SMEM>>>(pm);
    gemm_out<<<dim3(Cc/128, NTOK/128), 256, G_SMEM>>>(ctxh, wph, bp, out);
}

// round 14
// speedup vs baseline: 1.0347x; 1.0014x over previous
#include <cuda_runtime.h>
#include <cuda_fp16.h>
#include <cstdint>
#include <math.h>

#define Bb 2
#define Tt 2048
#define Cc 2048
#define Hh 16
#define Dd 128
#define NTOK (Bb*Tt)   // 4096

// Scratch (device globals: no runtime allocation allowed)
__device__ __half g_xh [(size_t)NTOK*Cc];
__device__ __half g_wqh[(size_t)Cc*Cc];
__device__ __half g_wkh[(size_t)Cc*Cc];
__device__ __half g_wvh[(size_t)Cc*Cc];
__device__ __half g_wph[(size_t)Cc*Cc];
__device__ __half g_qh [(size_t)NTOK*Cc];
__device__ __half g_kh [(size_t)NTOK*Cc];
__device__ __half g_vh [(size_t)NTOK*Cc];
__device__ __half g_ctxh[(size_t)NTOK*Cc];

// ===========================================================================
// helpers
// ===========================================================================
__device__ __forceinline__ uint32_t smem_u32(const void* p) {
    uint32_t a;
    asm("{ .reg .u64 t; cvta.to.shared.u64 t, %1; cvt.u32.u64 %0, t; }" : "=r"(a) : "l"(p));
    return a;
}
__device__ __forceinline__ void cp_async16(uint32_t dst, const void* src) {
    asm volatile("cp.async.cg.shared.global [%0], [%1], 16;" :: "r"(dst), "l"(src) : "memory");
}
__device__ __forceinline__ void cp_commit() {
    asm volatile("cp.async.commit_group;" ::: "memory");
}
__device__ __forceinline__ void cp_wait1() {
    asm volatile("cp.async.wait_group 1;" ::: "memory");
}
__device__ __forceinline__ void cp_wait0() {
    asm volatile("cp.async.wait_group 0;" ::: "memory");
}
__device__ __forceinline__ void ldsm_x4(uint32_t* r, uint32_t addr) {
    asm volatile("ldmatrix.sync.aligned.m8n8.x4.shared.b16 {%0,%1,%2,%3}, [%4];"
                 : "=r"(r[0]), "=r"(r[1]), "=r"(r[2]), "=r"(r[3]) : "r"(addr));
}
__device__ __forceinline__ void ldsm_x4_t(uint32_t* r, uint32_t addr) {
    asm volatile("ldmatrix.sync.aligned.m8n8.x4.trans.shared.b16 {%0,%1,%2,%3}, [%4];"
                 : "=r"(r[0]), "=r"(r[1]), "=r"(r[2]), "=r"(r[3]) : "r"(addr));
}
// m16n8k16 fp16 MMA, fp32 accumulate
__device__ __forceinline__ void mma_f16(float* c, const uint32_t* a, const uint32_t* b) {
    asm volatile(
        "mma.sync.aligned.m16n8k16.row.col.f32.f16.f16.f32 "
        "{%0,%1,%2,%3}, {%4,%5,%6,%7}, {%8,%9}, {%0,%1,%2,%3};"
        : "+f"(c[0]), "+f"(c[1]), "+f"(c[2]), "+f"(c[3])
        : "r"(a[0]), "r"(a[1]), "r"(a[2]), "r"(a[3]), "r"(b[0]), "r"(b[1]));
}
// raw MUFU ex2 (exp base 2); log2e folded into Wq so no multiply needed
__device__ __forceinline__ float exp2a(float x) {
    float y;
    asm("ex2.approx.f32 %0, %1;" : "=f"(y) : "f"(x));
    return y;
}

// ===========================================================================
// fp32 -> fp16 conversion; Wq gets (1/sqrt(D)) * log2(e) folded in
// ===========================================================================
__global__ void __launch_bounds__(256) tohalf_all(
    const float4* __restrict__ x,  __half* __restrict__ xr,
    const float4* __restrict__ w0, __half* __restrict__ r0,
    const float4* __restrict__ w1, __half* __restrict__ r1,
    const float4* __restrict__ w2, __half* __restrict__ r2,
    const float4* __restrict__ w3, __half* __restrict__ r3)
{
    const int z = blockIdx.z;
    const float4* src; __half* dst; int n4;
    float sc = 1.0f;
    if      (z == 0) { src = x;  dst = xr; n4 = NTOK*Cc/4; }
    else if (z == 1) { src = w0; dst = r0; n4 = Cc*Cc/4;
                       sc = 0.08838834764831845f * 1.4426950408889634f; }
    else if (z == 2) { src = w1; dst = r1; n4 = Cc*Cc/4; }
    else if (z == 3) { src = w2; dst = r2; n4 = Cc*Cc/4; }
    else             { src = w3; dst = r3; n4 = Cc*Cc/4; }
    int i = blockIdx.x * blockDim.x + threadIdx.x;
    if (i < n4) {
        float4 v = src[i];
        *(__half2*)(dst + (size_t)i*4)     = __floats2half2_rn(v.x*sc, v.y*sc);
        *(__half2*)(dst + (size_t)i*4 + 2) = __floats2half2_rn(v.z*sc, v.w*sc);
    }
}

// ===========================================================================
// fp16 mma.sync GEMM (unchanged): CTA 128x128, 256 thr, BK=64, 3 stages,
// 96KB smem -> 2 CTAs/SM.
// ===========================================================================
#define G_BK     64
#define G_TBY    (128*128)
#define G_STAGES 3
#define G_SMEM   (G_STAGES*2*G_TBY)            // 98304
#define G_NSTEP  (Cc / G_BK)                   // 32

template<bool HALF_OUT>
__device__ __forceinline__ void gemm_body(const __half* __restrict__ A,
                                          const __half* __restrict__ W,
                                          const float* __restrict__ bias,
                                          float* __restrict__ Cf,
                                          __half* __restrict__ Ch)
{
    extern __shared__ char smc[];
    const uint32_t asb = smem_u32(smc);
    const uint32_t bsb = asb + G_STAGES * G_TBY;

    const int tid  = threadIdx.x;
    const int lane = tid & 31;
    const int warp = tid >> 5;
    const int n0 = blockIdx.x * 128;
    const int m0 = blockIdx.y * 128;
    const int wm = (warp & 1) * 64;
    const int wn = (warp >> 1) * 32;
    const int fr = lane >> 2;
    const int fc = lane & 3;

    const int a_msel = (lane >> 3) & 1;
    const int a_ksel = lane >> 4;
    const int b_nsel = (lane >> 4) & 1;
    const int b_ksel = (lane >> 3) & 1;
    uint32_t a_off[4], a_sw[4], b_off[2], b_sw[2];
    #pragma unroll
    for (int mi = 0; mi < 4; mi++) {
        const int r = wm + mi*16 + a_msel*8 + (lane & 7);
        a_off[mi] = (uint32_t)r * 128;
        a_sw[mi]  = (uint32_t)(r & 7);
    }
    #pragma unroll
    for (int pi = 0; pi < 2; pi++) {
        const int n = wn + pi*16 + b_nsel*8 + (lane & 7);
        b_off[pi] = (uint32_t)n * 128;
        b_sw[pi]  = (uint32_t)(n & 7);
    }

    const int lr  = tid >> 1;
    const int lj0 = (tid & 1) * 4;
    const __half* Ag = A + (size_t)(m0 + lr) * Cc;
    const __half* Wg = W + (size_t)(n0 + lr) * Cc;
    const uint32_t swr = (uint32_t)(lr & 7);

    float acc[4][4][4];
    #pragma unroll
    for (int i = 0; i < 4; i++)
        #pragma unroll
        for (int j = 0; j < 4; j++)
            #pragma unroll
            for (int q = 0; q < 4; q++) acc[i][j][q] = 0.f;

    #define G_LOAD(s, st) do {                                                  \
        const uint32_t sa = asb + (st) * G_TBY;                                  \
        const uint32_t sb = bsb + (st) * G_TBY;                                  \
        const int kof = (s) * G_BK;                                              \
        _Pragma("unroll")                                                        \
        for (int j = 0; j < 4; j++) {                                            \
            const int ch = lj0 + j;                                              \
            const uint32_t dof = lr*128 + (((uint32_t)ch ^ swr) << 4);           \
            cp_async16(sa + dof, Ag + kof + ch*8);                               \
            cp_async16(sb + dof, Wg + kof + ch*8);                               \
        }                                                                        \
    } while (0)

    G_LOAD(0, 0); cp_commit();
    G_LOAD(1, 1); cp_commit();

    for (int s = 0; s < G_NSTEP; s++) {
        cp_wait1();
        __syncthreads();
        if (s + 2 < G_NSTEP) { G_LOAD(s + 2, (s + 2) % G_STAGES); }
        cp_commit();

        const uint32_t A_sa = asb + (s % G_STAGES) * G_TBY;
        const uint32_t B_sa = bsb + (s % G_STAGES) * G_TBY;

        #pragma unroll
        for (int ks = 0; ks < 4; ks++) {
            const uint32_t ka  = (uint32_t)(2*ks + a_ksel);
            const uint32_t kb_ = (uint32_t)(2*ks + b_ksel);
            uint32_t af[4][4], bf[2][4];
            #pragma unroll
            for (int mi = 0; mi < 4; mi++)
                ldsm_x4(af[mi], A_sa + a_off[mi] + ((ka ^ a_sw[mi]) << 4));
            #pragma unroll
            for (int pi = 0; pi < 2; pi++)
                ldsm_x4(bf[pi], B_sa + b_off[pi] + ((kb_ ^ b_sw[pi]) << 4));
            #pragma unroll
            for (int mi = 0; mi < 4; mi++)
                #pragma unroll
                for (int ni = 0; ni < 4; ni++)
                    mma_f16(acc[mi][ni], af[mi], &bf[ni >> 1][(ni & 1) * 2]);
        }
    }
    #undef G_LOAD
    __syncthreads();

    #pragma unroll
    for (int mi = 0; mi < 4; mi++) {
        const int r0 = m0 + wm + mi*16 + fr;
        #pragma unroll
        for (int ni = 0; ni < 4; ni++) {
            const int col = n0 + wn + ni*8 + fc*2;
            if (HALF_OUT) {
                *(__half2*)(Ch + (size_t)r0       * Cc + col) =
                    __floats2half2_rn(acc[mi][ni][0], acc[mi][ni][1]);
                *(__half2*)(Ch + (size_t)(r0 + 8) * Cc + col) =
                    __floats2half2_rn(acc[mi][ni][2], acc[mi][ni][3]);
            } else {
                const float b0 = __ldg(bias + col), b1 = __ldg(bias + col + 1);
                *(float2*)(Cf + (size_t)r0       * Cc + col) =
                    make_float2(acc[mi][ni][0] + b0, acc[mi][ni][1] + b1);
                *(float2*)(Cf + (size_t)(r0 + 8) * Cc + col) =
                    make_float2(acc[mi][ni][2] + b0, acc[mi][ni][3] + b1);
            }
        }
    }
}

__global__ void __launch_bounds__(256, 2)
gemm_out(const __half* __restrict__ A, const __half* __restrict__ W,
         const float* __restrict__ bias, float* __restrict__ C) {
    gemm_body<false>(A, W, bias, C, nullptr);
}

__global__ void __launch_bounds__(256, 2)
gemm_qkv(const __half* __restrict__ A,
         const __half* __restrict__ W0, const __half* __restrict__ W1,
         const __half* __restrict__ W2,
         __half* __restrict__ C0, __half* __restrict__ C1, __half* __restrict__ C2) {
    const __half* W = (blockIdx.z == 0) ? W0 : (blockIdx.z == 1) ? W1 : W2;
    __half*       C = (blockIdx.z == 0) ? C0 : (blockIdx.z == 1) ? C1 : C2;
    gemm_body<true>(A, W, nullptr, nullptr, C);
}

// ===========================================================================
// Flash-attention, fp16 mma.sync, double-buffered K/V (R10 structure).
// CTA = 128 threads, one (b,h,64-query tile). smem 88KB -> 2 CTAs/SM.
// Scale*log2e folded into Wq; softmax uses raw ex2.
// ===========================================================================
#define AT_Q  0
#define AT_K0 16384
#define AT_V0 49152
#define AT_P  81920
#define AT_SMEM 90112

__global__ void __launch_bounds__(128, 2) attn_f16(const int* __restrict__ pm)
{
    extern __shared__ char smc[];
    const uint32_t sb  = smem_u32(smc);
    const uint32_t qsb = sb + AT_Q;
    const uint32_t psb = sb + AT_P;

    const int qb = (gridDim.x - 1) - blockIdx.x;   // descending order
    const int h  = blockIdx.y;
    const int b  = blockIdx.z;
    const int tid  = threadIdx.x;
    const int lane = tid & 31;
    const int warp = tid >> 5;
    const int fr = lane >> 2;
    const int fc = lane & 3;

    const int a_msel = (lane >> 3) & 1;
    const int a_ksel = lane >> 4;
    const int b_nsel = (lane >> 4) & 1;
    const int b_ksel = (lane >> 3) & 1;
    const int v_ssel = (lane >> 3) & 1;
    const int v_dsel = (lane >> 4) & 1;
    const int a_row  = warp*16 + a_msel*8 + (lane & 7);

    const size_t hoff = (size_t)h * Dd;
    const __half* Qg = g_qh + (size_t)b * Tt * Cc + hoff;
    const __half* Kg = g_kh + (size_t)b * Tt * Cc + hoff;
    const __half* Vg = g_vh + (size_t)b * Tt * Cc + hoff;
    const int q0 = qb * 64;

    const int lrow = tid >> 1;
    const int lch0 = (tid & 1) * 8;
    const uint32_t lsw = (uint32_t)(lrow & 7);

    #define AT_LOADKV(kt, st) do {                                                 \
        const uint32_t kb_ = sb + AT_K0 + (st)*16384;                              \
        const uint32_t vb_ = sb + AT_V0 + (st)*16384;                              \
        _Pragma("unroll")                                                          \
        for (int j = 0; j < 8; j++) {                                              \
            const int ch = lch0 + j;                                               \
            const uint32_t doff = lrow*256 + (((uint32_t)ch ^ lsw) << 4);          \
            cp_async16(kb_ + doff, Kg + (size_t)((kt)*64 + lrow)*Cc + ch*8);       \
            cp_async16(vb_ + doff, Vg + (size_t)((kt)*64 + lrow)*Cc + ch*8);       \
        }                                                                          \
        cp_commit();                                                               \
    } while (0)

    #pragma unroll
    for (int j = 0; j < 8; j++) {
        const int ch = lch0 + j;
        cp_async16(qsb + lrow*256 + (((uint32_t)ch ^ lsw) << 4),
                   Qg + (size_t)(q0 + lrow)*Cc + ch*8);
    }
    cp_commit();
    AT_LOADKV(0, 0);
    cp_wait1();
    __syncthreads();

    uint32_t qf[8][4];
    #pragma unroll
    for (int kb = 0; kb < 8; kb++)
        ldsm_x4(qf[kb], qsb + a_row*256 + (((uint32_t)(2*kb + a_ksel) ^ (uint32_t)(a_row & 7)) << 4));

    const int rowA = q0 + warp*16 + fr;
    const int rowB = rowA + 8;
    const int pmA = pm[b*Tt + rowA];
    const int pmB = pm[b*Tt + rowB];
    const int prA = warp*16 + fr;

    float o[16][4];
    #pragma unroll
    for (int i = 0; i < 16; i++)
        #pragma unroll
        for (int j = 0; j < 4; j++) o[i][j] = 0.f;
    float mA = -INFINITY, mB = -INFINITY, lA = 0.f, lB = 0.f;

    for (int kt = 0; kt <= qb; kt++) {
        const int cur = kt & 1;
        const bool more = (kt + 1 <= qb);
        if (more) AT_LOADKV(kt + 1, cur ^ 1);
        if (more) cp_wait1(); else cp_wait0();
        __syncthreads();

        const uint32_t ksb = sb + AT_K0 + cur*16384;
        const uint32_t vsb = sb + AT_V0 + cur*16384;

        // ---- S = Q K^T (scale*log2e pre-folded into q) ----
        float sa[8][4];
        #pragma unroll
        for (int ni = 0; ni < 8; ni++)
            #pragma unroll
            for (int j = 0; j < 4; j++) sa[ni][j] = 0.f;

        #pragma unroll
        for (int kb = 0; kb < 8; kb++) {
            uint32_t bq[4][4];
            #pragma unroll
            for (int pi = 0; pi < 4; pi++) {
                const int n = pi*16 + b_nsel*8 + (lane & 7);
                ldsm_x4(bq[pi], ksb + n*256 + (((uint32_t)(2*kb + b_ksel) ^ (uint32_t)(n & 7)) << 4));
            }
            #pragma unroll
            for (int ni = 0; ni < 8; ni++)
                mma_f16(sa[ni], qf[kb], &bq[ni >> 1][(ni & 1) * 2]);
        }

        // ---- mask + online softmax (base-2 domain) ----
        float mxA = -INFINITY, mxB = -INFINITY;
        #pragma unroll
        for (int ni = 0; ni < 8; ni++) {
            const int c0 = kt*64 + ni*8 + 2*fc;
            float s0 = sa[ni][0], s1 = sa[ni][1];
            float s2 = sa[ni][2], s3 = sa[ni][3];
            if (pmA == 0) { s0 = -1e9f; s1 = -1e9f; }
            if (pmB == 0) { s2 = -1e9f; s3 = -1e9f; }
            if (kt == qb) {
                if (c0     > rowA) s0 = -INFINITY;
                if (c0 + 1 > rowA) s1 = -INFINITY;
                if (c0     > rowB) s2 = -INFINITY;
                if (c0 + 1 > rowB) s3 = -INFINITY;
            }
            sa[ni][0] = s0; sa[ni][1] = s1; sa[ni][2] = s2; sa[ni][3] = s3;
            mxA = fmaxf(mxA, fmaxf(s0, s1));
            mxB = fmaxf(mxB, fmaxf(s2, s3));
        }
        mxA = fmaxf(mxA, __shfl_xor_sync(0xffffffffu, mxA, 1));
        mxA = fmaxf(mxA, __shfl_xor_sync(0xffffffffu, mxA, 2));
        mxB = fmaxf(mxB, __shfl_xor_sync(0xffffffffu, mxB, 1));
        mxB = fmaxf(mxB, __shfl_xor_sync(0xffffffffu, mxB, 2));

        const float mnA = fmaxf(mA, mxA), mnB = fmaxf(mB, mxB);
        const float sfA = exp2a(mA - mnA), sfB = exp2a(mB - mnB);
        mA = mnA; mB = mnB;

        float suA = 0.f, suB = 0.f;
        #pragma unroll
        for (int ni = 0; ni < 8; ni++) {
            __half2 h01 = __floats2half2_rn(exp2a(sa[ni][0] - mA), exp2a(sa[ni][1] - mA));
            __half2 h23 = __floats2half2_rn(exp2a(sa[ni][2] - mB), exp2a(sa[ni][3] - mB));
            const float2 f01 = __half22float2(h01);
            const float2 f23 = __half22float2(h23);
            suA += f01.x + f01.y; suB += f23.x + f23.y;
            const uint32_t aoA = psb + prA*128     + (((uint32_t)ni ^ (uint32_t)(prA & 7))     << 4) + fc*4;
            const uint32_t aoB = psb + (prA+8)*128 + (((uint32_t)ni ^ (uint32_t)((prA+8) & 7)) << 4) + fc*4;
            *(__half2*)(smc + (aoA - sb)) = h01;
            *(__half2*)(smc + (aoB - sb)) = h23;
        }
        suA += __shfl_xor_sync(0xffffffffu, suA, 1);
        suA += __shfl_xor_sync(0xffffffffu, suA, 2);
        suB += __shfl_xor_sync(0xffffffffu, suB, 1);
        suB += __shfl_xor_sync(0xffffffffu, suB, 2);
        lA = lA*sfA + suA;
        lB = lB*sfB + suB;
        #pragma unroll
        for (int ni = 0; ni < 16; ni++) {
            o[ni][0] *= sfA; o[ni][1] *= sfA;
            o[ni][2] *= sfB; o[ni][3] *= sfB;
        }
        __syncwarp();

        #pragma unroll
        for (int kb = 0; kb < 4; kb++) {
            uint32_t pa[4];
            ldsm_x4(pa, psb + a_row*128 + (((uint32_t)(2*kb + a_ksel) ^ (uint32_t)(a_row & 7)) << 4));
            #pragma unroll
            for (int di = 0; di < 8; di++) {
                uint32_t bv[4];
                const int sv = kb*16 + v_ssel*8 + (lane & 7);
                const uint32_t ch = (uint32_t)(2*di + v_dsel);
                ldsm_x4_t(bv, vsb + sv*256 + ((ch ^ (uint32_t)(sv & 7)) << 4));
                mma_f16(o[di*2    ], pa, &bv[0]);
                mma_f16(o[di*2 + 1], pa, &bv[2]);
            }
        }
        __syncthreads();
    }
    #undef AT_LOADKV

    const float iA = 1.f / lA, iB = 1.f / lB;
    __half* cpA = g_ctxh + (size_t)(b*Tt + rowA)*Cc + hoff;
    __half* cpB = g_ctxh + (size_t)(b*Tt + rowB)*Cc + hoff;
    #pragma unroll
    for (int ni = 0; ni < 16; ni++) {
        const int d0 = ni*8 + 2*fc;
        *(__half2*)(cpA + d0) = __floats2half2_rn(o[ni][0]*iA, o[ni][1]*iA);
        *(__half2*)(cpB + d0) = __floats2half2_rn(o[ni][2]*iB, o[ni][3]*iB);
    }
}

// ===========================================================================
extern "C" void kernel_launch(void* const* d_in, const int* in_sizes, int n_in,
                              void* d_out, int out_size)
{
    (void)in_sizes; (void)n_in; (void)out_size;
    const float* x  = (const float*)d_in[0];
    const int*   pm = (const int*)  d_in[1];
    const float* Wq = (const float*)d_in[2];
    const float* Wk = (const float*)d_in[3];
    const float* Wv = (const float*)d_in[4];
    const float* Wp = (const float*)d_in[5];
    const float* bp = (const float*)d_in[6];
    float* out = (float*)d_out;

    __half *xh, *wqh, *wkh, *wvh, *wph, *qh, *kh, *vh, *ctxh;
    cudaGetSymbolAddress((void**)&xh,   g_xh);
    cudaGetSymbolAddress((void**)&wqh,  g_wqh);
    cudaGetSymbolAddress((void**)&wkh,  g_wkh);
    cudaGetSymbolAddress((void**)&wvh,  g_wvh);
    cudaGetSymbolAddress((void**)&wph,  g_wph);
    cudaGetSymbolAddress((void**)&qh,   g_qh);
    cudaGetSymbolAddress((void**)&kh,   g_kh);
    cudaGetSymbolAddress((void**)&vh,   g_vh);
    cudaGetSymbolAddress((void**)&ctxh, g_ctxh);

    const int nb = (NTOK*Cc/4 + 255) / 256;
    tohalf_all<<<dim3(nb, 1, 5), 256>>>(
        (const float4*)x,  xh,
        (const float4*)Wq, wqh,
        (const float4*)Wk, wkh,
        (const float4*)Wv, wvh,
        (const float4*)Wp, wph);

    cudaFuncSetAttribute(gemm_qkv, cudaFuncAttributeMaxDynamicSharedMemorySize, G_SMEM);
    cudaFuncSetAttribute(gemm_out, cudaFuncAttributeMaxDynamicSharedMemorySize, G_SMEM);
    cudaFuncSetAttribute(attn_f16, cudaFuncAttributeMaxDynamicSharedMemorySize, AT_SMEM);

    gemm_qkv<<<dim3(Cc/128, NTOK/128, 3), 256, G_SMEM>>>(xh, wqh, wkh, wvh, qh, kh, vh);
    attn_f16<<<dim3(Tt/64, Hh, Bb), 128, AT_SMEM>>>(pm);
    gemm_out<<<dim3(Cc/128, NTOK/128), 256, G_SMEM>>>(ctxh, wph, bp, out);
}